// round 13
// baseline (speedup 1.0000x reference)
#include <cuda_runtime.h>
#include <cuda_bf16.h>
#include <math.h>

// Problem dims (fixed per reference)
#define Nb 16
#define Vn 16384
#define Dd 128
#define Ee 65536
#define Ll 2
#define Mrows (Nb * Vn)            // 262144
#define VD (Vn * Dd)               // 2097152
#define GEMM_BLOCKS (Mrows / 128)  // 2048
#define EPSBN 1e-5

// ---------------- scratch (device globals; no allocations allowed) ----------------
__device__ float g_nei[Nb * Vn * Dd];       // SpMM output (X_nei)
__device__ float g_x1[Nb * Vn * Dd];        // layer-0 activation buffer
__device__ float g_partial[GEMM_BLOCKS * 2 * Dd]; // per-block (sum, sumsq) per feature
__device__ float g_scale[Dd];
__device__ float g_shift[Dd];
__device__ int   g_rowptr[Vn + 1];
__device__ int   g_cursor[Vn];
__device__ int   g_eid[Ee];

// ---------------- CSR build ----------------
__global__ void k_zero_counts() {
    int v = blockIdx.x * blockDim.x + threadIdx.x;
    if (v < Vn) g_cursor[v] = 0;
}

__global__ void k_hist(const int* __restrict__ dst) {
    int e = blockIdx.x * blockDim.x + threadIdx.x;
    if (e < Ee) atomicAdd(&g_cursor[dst[e]], 1);
}

// single-block scan: 512 threads x 32 elements = 16384
__global__ void k_scan() {
    __shared__ int s[512];
    int tid = threadIdx.x;
    int base = tid * 32;
    int local = 0;
#pragma unroll
    for (int i = 0; i < 32; ++i) local += g_cursor[base + i];
    s[tid] = local;
    __syncthreads();
    for (int off = 1; off < 512; off <<= 1) {
        int v = s[tid];
        int add = (tid >= off) ? s[tid - off] : 0;
        __syncthreads();
        s[tid] = v + add;
        __syncthreads();
    }
    int run = s[tid] - local; // exclusive prefix for this chunk
    for (int i = 0; i < 32; ++i) {
        int c = g_cursor[base + i];
        g_rowptr[base + i] = run;
        g_cursor[base + i] = run; // reuse as fill cursor
        run += c;
    }
    if (tid == 511) g_rowptr[Vn] = run; // == Ee
}

__global__ void k_fill(const int* __restrict__ dst) {
    int e = blockIdx.x * blockDim.x + threadIdx.x;
    if (e < Ee) {
        int p = atomicAdd(&g_cursor[dst[e]], 1);
        g_eid[p] = e;
    }
}

// make accumulation order deterministic: sort each row's edge-id list ascending
__global__ void k_sortrows() {
    int v = blockIdx.x * blockDim.x + threadIdx.x;
    if (v >= Vn) return;
    int b = g_rowptr[v], en = g_rowptr[v + 1];
    for (int i = b + 1; i < en; ++i) {
        int key = g_eid[i];
        int j = i - 1;
        while (j >= b && g_eid[j] > key) { g_eid[j + 1] = g_eid[j]; --j; }
        g_eid[j + 1] = key;
    }
}

// ---------------- SpMM: X_nei[n, v, :] = sum_{e: dst=v} A[e] * X[n, src[e], :] ----------------
// one block per v, 128 threads = feature dim, 16 accumulators per thread (batch dim)
__global__ void k_spmm(const float* __restrict__ Xext, int use_ext,
                       const float* __restrict__ Avals, const int* __restrict__ esrc) {
    const float* __restrict__ X = use_ext ? Xext : g_x1;
    int v = blockIdx.x;
    int d = threadIdx.x;
    int beg = g_rowptr[v], end = g_rowptr[v + 1];

    float acc[Nb];
#pragma unroll
    for (int n = 0; n < Nb; ++n) acc[n] = 0.0f;

    __shared__ int   s_src[128];
    __shared__ float s_a[128];

    for (int cb = beg; cb < end; cb += 128) {
        int cnt = min(128, end - cb);
        __syncthreads();
        if (d < cnt) {
            int e = g_eid[cb + d];
            s_src[d] = esrc[e];
            s_a[d] = Avals[e];
        }
        __syncthreads();
        for (int t = 0; t < cnt; ++t) {
            float a = s_a[t];
            int base = s_src[t] * Dd + d;
#pragma unroll
            for (int n = 0; n < Nb; ++n)
                acc[n] += a * X[base + n * VD];
        }
    }
    int ob = v * Dd + d;
#pragma unroll
    for (int n = 0; n < Nb; ++n) g_nei[ob + n * VD] = acc[n];
}

// ---------------- GEMM: Y = X @ Ws^T + X_nei @ Wn^T  (+ fused BN stat partials) ----------------
// 128x128 output tile / block, BK=8, 256 threads, 8x8 micro-tile per thread.
__global__ void __launch_bounds__(256, 2)
k_gemm(const float* __restrict__ Xext, int x_ext,
       const float* __restrict__ W0, const float* __restrict__ W1,
       float* __restrict__ Yext, int y_ext) {
    const float* __restrict__ X0 = x_ext ? Xext : g_x1;
    float* __restrict__ Y = y_ext ? Yext : g_x1;

    __shared__ float As[8][128];
    __shared__ float Bs[8][128];
    __shared__ float s_sum[16][128];
    __shared__ float s_sq[16][128];

    int tid = threadIdx.x;
    int bx = blockIdx.x;
    int row0 = bx * 128;
    int tx = tid & 15;        // 0..15 -> cols tx*8..tx*8+7
    int ty = tid >> 4;        // 0..15 -> rows ty*8..ty*8+7
    int lr = tid >> 1;        // 0..127 loader row
    int lc = (tid & 1) * 4;   // 0 or 4 loader col

    float acc[8][8];
#pragma unroll
    for (int i = 0; i < 8; ++i)
#pragma unroll
        for (int j = 0; j < 8; ++j) acc[i][j] = 0.0f;

    const float* Xi[2] = {X0, g_nei};
    const float* Wi[2] = {W0, W1};

    for (int s = 0; s < 2; ++s) {
        const float* __restrict__ Xp = Xi[s];
        const float* __restrict__ Wp = Wi[s];
        for (int k0 = 0; k0 < 128; k0 += 8) {
            float4 av = *(const float4*)(Xp + (row0 + lr) * Dd + k0 + lc);
            float4 bv = *(const float4*)(Wp + lr * Dd + k0 + lc);
            __syncthreads();
            As[lc + 0][lr] = av.x; As[lc + 1][lr] = av.y;
            As[lc + 2][lr] = av.z; As[lc + 3][lr] = av.w;
            Bs[lc + 0][lr] = bv.x; Bs[lc + 1][lr] = bv.y;
            Bs[lc + 2][lr] = bv.z; Bs[lc + 3][lr] = bv.w;
            __syncthreads();
#pragma unroll
            for (int kk = 0; kk < 8; ++kk) {
                float a[8], b[8];
                *(float4*)(a)     = *(const float4*)&As[kk][ty * 8];
                *(float4*)(a + 4) = *(const float4*)&As[kk][ty * 8 + 4];
                *(float4*)(b)     = *(const float4*)&Bs[kk][tx * 8];
                *(float4*)(b + 4) = *(const float4*)&Bs[kk][tx * 8 + 4];
#pragma unroll
                for (int i = 0; i < 8; ++i)
#pragma unroll
                    for (int j = 0; j < 8; ++j)
                        acc[i][j] += a[i] * b[j];
            }
        }
    }

    // write Y
#pragma unroll
    for (int i = 0; i < 8; ++i) {
        int row = row0 + ty * 8 + i;
        float4 v0 = make_float4(acc[i][0], acc[i][1], acc[i][2], acc[i][3]);
        float4 v1 = make_float4(acc[i][4], acc[i][5], acc[i][6], acc[i][7]);
        *(float4*)(Y + row * Dd + tx * 8)     = v0;
        *(float4*)(Y + row * Dd + tx * 8 + 4) = v1;
    }

    // deterministic per-block BN stats: per-thread column sums -> smem -> fixed-order reduce
#pragma unroll
    for (int j = 0; j < 8; ++j) {
        float sv = 0.0f, qv = 0.0f;
#pragma unroll
        for (int i = 0; i < 8; ++i) { sv += acc[i][j]; qv += acc[i][j] * acc[i][j]; }
        s_sum[ty][tx * 8 + j] = sv;
        s_sq[ty][tx * 8 + j] = qv;
    }
    __syncthreads();
    if (tid < 128) {
        float sv = 0.0f, qv = 0.0f;
#pragma unroll
        for (int r = 0; r < 16; ++r) { sv += s_sum[r][tid]; qv += s_sq[r][tid]; }
        g_partial[bx * 256 + tid] = sv;
        g_partial[bx * 256 + 128 + tid] = qv;
    }
}

// ---------------- BN finalize: reduce partials (double), compute scale/shift ----------------
__global__ void k_bn_finalize(const float* __restrict__ gamma, const float* __restrict__ beta) {
    int d = threadIdx.x; // 128
    double s = 0.0, q = 0.0;
    for (int b = 0; b < GEMM_BLOCKS; ++b) {
        s += (double)g_partial[b * 256 + d];
        q += (double)g_partial[b * 256 + 128 + d];
    }
    const double M = (double)Mrows;
    double mean = s / M;
    double var = q / M - mean * mean;
    float sc = gamma[d] * (float)(1.0 / sqrt(var + EPSBN));
    g_scale[d] = sc;
    g_shift[d] = beta[d] - (float)mean * sc;
}

// ---------------- BN apply + ReLU (in place) ----------------
__global__ void k_bn_relu(float* __restrict__ Yext, int y_ext) {
    float* __restrict__ Y = y_ext ? Yext : g_x1;
    int i = blockIdx.x * blockDim.x + threadIdx.x; // over Mrows*Dd/4 float4s
    float4 y = ((const float4*)Y)[i];
    int d = (i & 31) * 4;
    y.x = fmaxf(0.0f, y.x * g_scale[d + 0] + g_shift[d + 0]);
    y.y = fmaxf(0.0f, y.y * g_scale[d + 1] + g_shift[d + 1]);
    y.z = fmaxf(0.0f, y.z * g_scale[d + 2] + g_shift[d + 2]);
    y.w = fmaxf(0.0f, y.w * g_scale[d + 3] + g_shift[d + 3]);
    ((float4*)Y)[i] = y;
}

// ---------------- launch ----------------
extern "C" void kernel_launch(void* const* d_in, const int* in_sizes, int n_in,
                              void* d_out, int out_size) {
    const float* H     = (const float*)d_in[0];
    const int*   esrc  = (const int*)d_in[1];
    const int*   edst  = (const int*)d_in[2];
    const float* Av    = (const float*)d_in[3];
    const float* Wself = (const float*)d_in[4];
    const float* Wnei  = (const float*)d_in[5];
    const float* gamma = (const float*)d_in[6];
    const float* beta  = (const float*)d_in[7];
    float* out = (float*)d_out;

    // CSR build (graph is an input; rebuild every launch, deterministic via row sort)
    k_zero_counts<<<Vn / 256, 256>>>();
    k_hist<<<Ee / 256, 256>>>(edst);
    k_scan<<<1, 512>>>();
    k_fill<<<Ee / 256, 256>>>(edst);
    k_sortrows<<<Vn / 128, 128>>>();

    for (int l = 0; l < Ll; ++l) {
        int x_ext = (l == 0) ? 1 : 0;      // layer 0 reads H, layer 1 reads g_x1
        int y_ext = (l == Ll - 1) ? 1 : 0; // last layer writes d_out, else g_x1
        k_spmm<<<Vn, 128>>>(H, x_ext, Av, esrc);
        k_gemm<<<GEMM_BLOCKS, 256>>>(H, x_ext,
                                     Wself + (size_t)l * Dd * Dd,
                                     Wnei  + (size_t)l * Dd * Dd,
                                     out, y_ext);
        k_bn_finalize<<<1, 128>>>(gamma + l * Dd, beta + l * Dd);
        k_bn_relu<<<(Mrows * Dd / 4) / 256, 256>>>(out, y_ext);
    }
}

// round 14
// speedup vs baseline: 1.0379x; 1.0379x over previous
#include <cuda_runtime.h>
#include <cuda_bf16.h>
#include <math.h>

// Problem dims (fixed per reference)
#define Nb 16
#define Vn 16384
#define Dd 128
#define Ee 65536
#define Ll 2
#define Mrows (Nb * Vn)            // 262144
#define VD (Vn * Dd)               // 2097152
#define GEMM_BLOCKS (Mrows / 128)  // 2048
#define EPSBN 1e-5

// ---------------- scratch (device globals; no allocations allowed) ----------------
__device__ float g_nei[Nb * Vn * Dd];       // SpMM output (X_nei)
__device__ float g_x1[Nb * Vn * Dd];        // layer-0 activation buffer
__device__ float g_partial[GEMM_BLOCKS * 2 * Dd]; // per-block (sum, sumsq) per feature
__device__ float g_scale[Dd];
__device__ float g_shift[Dd];
__device__ int   g_rowptr[Vn + 1];
__device__ int   g_cursor[Vn];
__device__ int   g_eid[Ee];

// ---------------- CSR build ----------------
__global__ void k_zero_counts() {
    int v = blockIdx.x * blockDim.x + threadIdx.x;
    if (v < Vn) g_cursor[v] = 0;
}

__global__ void k_hist(const int* __restrict__ dst) {
    int e = blockIdx.x * blockDim.x + threadIdx.x;
    if (e < Ee) atomicAdd(&g_cursor[dst[e]], 1);
}

// single-block scan: 512 threads x 32 elements = 16384
__global__ void k_scan() {
    __shared__ int s[512];
    int tid = threadIdx.x;
    int base = tid * 32;
    int local = 0;
#pragma unroll
    for (int i = 0; i < 32; ++i) local += g_cursor[base + i];
    s[tid] = local;
    __syncthreads();
    for (int off = 1; off < 512; off <<= 1) {
        int v = s[tid];
        int add = (tid >= off) ? s[tid - off] : 0;
        __syncthreads();
        s[tid] = v + add;
        __syncthreads();
    }
    int run = s[tid] - local; // exclusive prefix for this chunk
    for (int i = 0; i < 32; ++i) {
        int c = g_cursor[base + i];
        g_rowptr[base + i] = run;
        g_cursor[base + i] = run; // reuse as fill cursor
        run += c;
    }
    if (tid == 511) g_rowptr[Vn] = run; // == Ee
}

__global__ void k_fill(const int* __restrict__ dst) {
    int e = blockIdx.x * blockDim.x + threadIdx.x;
    if (e < Ee) {
        int p = atomicAdd(&g_cursor[dst[e]], 1);
        g_eid[p] = e;
    }
}

// make accumulation order deterministic: sort each row's edge-id list ascending
__global__ void k_sortrows() {
    int v = blockIdx.x * blockDim.x + threadIdx.x;
    if (v >= Vn) return;
    int b = g_rowptr[v], en = g_rowptr[v + 1];
    for (int i = b + 1; i < en; ++i) {
        int key = g_eid[i];
        int j = i - 1;
        while (j >= b && g_eid[j] > key) { g_eid[j + 1] = g_eid[j]; --j; }
        g_eid[j + 1] = key;
    }
}

// ---------------- SpMM: X_nei[n, v, :] = sum_{e: dst=v} A[e] * X[n, src[e], :] ----------------
// one block per v, 128 threads = feature dim, 16 accumulators per thread (batch dim)
__global__ void k_spmm(const float* __restrict__ Xext, int use_ext,
                       const float* __restrict__ Avals, const int* __restrict__ esrc) {
    const float* __restrict__ X = use_ext ? Xext : g_x1;
    int v = blockIdx.x;
    int d = threadIdx.x;
    int beg = g_rowptr[v], end = g_rowptr[v + 1];

    float acc[Nb];
#pragma unroll
    for (int n = 0; n < Nb; ++n) acc[n] = 0.0f;

    __shared__ int   s_src[128];
    __shared__ float s_a[128];

    for (int cb = beg; cb < end; cb += 128) {
        int cnt = min(128, end - cb);
        __syncthreads();
        if (d < cnt) {
            int e = g_eid[cb + d];
            s_src[d] = esrc[e];
            s_a[d] = Avals[e];
        }
        __syncthreads();
        for (int t = 0; t < cnt; ++t) {
            float a = s_a[t];
            int base = s_src[t] * Dd + d;
#pragma unroll
            for (int n = 0; n < Nb; ++n)
                acc[n] += a * X[base + n * VD];
        }
    }
    int ob = v * Dd + d;
#pragma unroll
    for (int n = 0; n < Nb; ++n) g_nei[ob + n * VD] = acc[n];
}

// ---------------- GEMM: Y = X @ Ws^T + X_nei @ Wn^T  (+ fused BN stat partials) ----------------
// 128x128 output tile / block, BK=8, 256 threads, 8x8 micro-tile per thread.
__global__ void __launch_bounds__(256, 2)
k_gemm(const float* __restrict__ Xext, int x_ext,
       const float* __restrict__ W0, const float* __restrict__ W1,
       float* __restrict__ Yext, int y_ext) {
    const float* __restrict__ X0 = x_ext ? Xext : g_x1;
    float* __restrict__ Y = y_ext ? Yext : g_x1;

    __shared__ float As[8][128];
    __shared__ float Bs[8][128];
    __shared__ float s_sum[16][128];
    __shared__ float s_sq[16][128];

    int tid = threadIdx.x;
    int bx = blockIdx.x;
    int row0 = bx * 128;
    int tx = tid & 15;        // 0..15 -> cols tx*8..tx*8+7
    int ty = tid >> 4;        // 0..15 -> rows ty*8..ty*8+7
    int lr = tid >> 1;        // 0..127 loader row
    int lc = (tid & 1) * 4;   // 0 or 4 loader col

    float acc[8][8];
#pragma unroll
    for (int i = 0; i < 8; ++i)
#pragma unroll
        for (int j = 0; j < 8; ++j) acc[i][j] = 0.0f;

    const float* Xi[2] = {X0, g_nei};
    const float* Wi[2] = {W0, W1};

    for (int s = 0; s < 2; ++s) {
        const float* __restrict__ Xp = Xi[s];
        const float* __restrict__ Wp = Wi[s];
        for (int k0 = 0; k0 < 128; k0 += 8) {
            float4 av = *(const float4*)(Xp + (row0 + lr) * Dd + k0 + lc);
            float4 bv = *(const float4*)(Wp + lr * Dd + k0 + lc);
            __syncthreads();
            As[lc + 0][lr] = av.x; As[lc + 1][lr] = av.y;
            As[lc + 2][lr] = av.z; As[lc + 3][lr] = av.w;
            Bs[lc + 0][lr] = bv.x; Bs[lc + 1][lr] = bv.y;
            Bs[lc + 2][lr] = bv.z; Bs[lc + 3][lr] = bv.w;
            __syncthreads();
#pragma unroll
            for (int kk = 0; kk < 8; ++kk) {
                float a[8], b[8];
                *(float4*)(a)     = *(const float4*)&As[kk][ty * 8];
                *(float4*)(a + 4) = *(const float4*)&As[kk][ty * 8 + 4];
                *(float4*)(b)     = *(const float4*)&Bs[kk][tx * 8];
                *(float4*)(b + 4) = *(const float4*)&Bs[kk][tx * 8 + 4];
#pragma unroll
                for (int i = 0; i < 8; ++i)
#pragma unroll
                    for (int j = 0; j < 8; ++j)
                        acc[i][j] += a[i] * b[j];
            }
        }
    }

    // write Y
#pragma unroll
    for (int i = 0; i < 8; ++i) {
        int row = row0 + ty * 8 + i;
        float4 v0 = make_float4(acc[i][0], acc[i][1], acc[i][2], acc[i][3]);
        float4 v1 = make_float4(acc[i][4], acc[i][5], acc[i][6], acc[i][7]);
        *(float4*)(Y + row * Dd + tx * 8)     = v0;
        *(float4*)(Y + row * Dd + tx * 8 + 4) = v1;
    }

    // deterministic per-block BN stats: per-thread column sums -> smem -> fixed-order reduce
#pragma unroll
    for (int j = 0; j < 8; ++j) {
        float sv = 0.0f, qv = 0.0f;
#pragma unroll
        for (int i = 0; i < 8; ++i) { sv += acc[i][j]; qv += acc[i][j] * acc[i][j]; }
        s_sum[ty][tx * 8 + j] = sv;
        s_sq[ty][tx * 8 + j] = qv;
    }
    __syncthreads();
    if (tid < 128) {
        float sv = 0.0f, qv = 0.0f;
#pragma unroll
        for (int r = 0; r < 16; ++r) { sv += s_sum[r][tid]; qv += s_sq[r][tid]; }
        g_partial[bx * 256 + tid] = sv;
        g_partial[bx * 256 + 128 + tid] = qv;
    }
}

// ---------------- BN finalize: reduce partials (double), compute scale/shift ----------------
__global__ void k_bn_finalize(const float* __restrict__ gamma, const float* __restrict__ beta) {
    int d = threadIdx.x; // 128
    double s = 0.0, q = 0.0;
    for (int b = 0; b < GEMM_BLOCKS; ++b) {
        s += (double)g_partial[b * 256 + d];
        q += (double)g_partial[b * 256 + 128 + d];
    }
    const double M = (double)Mrows;
    double mean = s / M;
    double var = q / M - mean * mean;
    float sc = gamma[d] * (float)(1.0 / sqrt(var + EPSBN));
    g_scale[d] = sc;
    g_shift[d] = beta[d] - (float)mean * sc;
}

// ---------------- BN apply + ReLU (in place) ----------------
__global__ void k_bn_relu(float* __restrict__ Yext, int y_ext) {
    float* __restrict__ Y = y_ext ? Yext : g_x1;
    int i = blockIdx.x * blockDim.x + threadIdx.x; // over Mrows*Dd/4 float4s
    float4 y = ((const float4*)Y)[i];
    int d = (i & 31) * 4;
    y.x = fmaxf(0.0f, y.x * g_scale[d + 0] + g_shift[d + 0]);
    y.y = fmaxf(0.0f, y.y * g_scale[d + 1] + g_shift[d + 1]);
    y.z = fmaxf(0.0f, y.z * g_scale[d + 2] + g_shift[d + 2]);
    y.w = fmaxf(0.0f, y.w * g_scale[d + 3] + g_shift[d + 3]);
    ((float4*)Y)[i] = y;
}

// ---------------- launch ----------------
extern "C" void kernel_launch(void* const* d_in, const int* in_sizes, int n_in,
                              void* d_out, int out_size) {
    const float* H     = (const float*)d_in[0];
    const int*   esrc  = (const int*)d_in[1];
    const int*   edst  = (const int*)d_in[2];
    const float* Av    = (const float*)d_in[3];
    const float* Wself = (const float*)d_in[4];
    const float* Wnei  = (const float*)d_in[5];
    const float* gamma = (const float*)d_in[6];
    const float* beta  = (const float*)d_in[7];
    float* out = (float*)d_out;

    // CSR build (graph is an input; rebuild every launch, deterministic via row sort)
    k_zero_counts<<<Vn / 256, 256>>>();
    k_hist<<<Ee / 256, 256>>>(edst);
    k_scan<<<1, 512>>>();
    k_fill<<<Ee / 256, 256>>>(edst);
    k_sortrows<<<Vn / 128, 128>>>();

    for (int l = 0; l < Ll; ++l) {
        int x_ext = (l == 0) ? 1 : 0;      // layer 0 reads H, layer 1 reads g_x1
        int y_ext = (l == Ll - 1) ? 1 : 0; // last layer writes d_out, else g_x1
        k_spmm<<<Vn, 128>>>(H, x_ext, Av, esrc);
        k_gemm<<<GEMM_BLOCKS, 256>>>(H, x_ext,
                                     Wself + (size_t)l * Dd * Dd,
                                     Wnei  + (size_t)l * Dd * Dd,
                                     out, y_ext);
        k_bn_finalize<<<1, 128>>>(gamma + l * Dd, beta + l * Dd);
        k_bn_relu<<<(Mrows * Dd / 4) / 256, 256>>>(out, y_ext);
    }
}

// round 15
// speedup vs baseline: 1.0418x; 1.0037x over previous
#include <cuda_runtime.h>
#include <cuda_bf16.h>
#include <math.h>

// Problem dims (fixed per reference)
#define Nb 16
#define Vn 16384
#define Dd 128
#define Ee 65536
#define Ll 2
#define Mrows (Nb * Vn)            // 262144
#define VD (Vn * Dd)               // 2097152
#define GEMM_BLOCKS (Mrows / 128)  // 2048
#define EPSBN 1e-5

// ---------------- scratch (device globals; no allocations allowed) ----------------
__device__ float g_nei[Nb * Vn * Dd];       // SpMM output (X_nei)
__device__ float g_x1[Nb * Vn * Dd];        // layer-0 activation buffer
__device__ float g_partial[GEMM_BLOCKS * 2 * Dd]; // per-block (sum, sumsq) per feature
__device__ float g_scale[Dd];
__device__ float g_shift[Dd];
__device__ int   g_rowptr[Vn + 1];
__device__ int   g_cursor[Vn];
__device__ int   g_eid[Ee];

// ---------------- CSR build ----------------
__global__ void k_zero_counts() {
    int v = blockIdx.x * blockDim.x + threadIdx.x;
    if (v < Vn) g_cursor[v] = 0;
}

__global__ void k_hist(const int* __restrict__ dst) {
    int e = blockIdx.x * blockDim.x + threadIdx.x;
    if (e < Ee) atomicAdd(&g_cursor[dst[e]], 1);
}

// single-block scan: 512 threads x 32 elements = 16384
__global__ void k_scan() {
    __shared__ int s[512];
    int tid = threadIdx.x;
    int base = tid * 32;
    int local = 0;
#pragma unroll
    for (int i = 0; i < 32; ++i) local += g_cursor[base + i];
    s[tid] = local;
    __syncthreads();
    for (int off = 1; off < 512; off <<= 1) {
        int v = s[tid];
        int add = (tid >= off) ? s[tid - off] : 0;
        __syncthreads();
        s[tid] = v + add;
        __syncthreads();
    }
    int run = s[tid] - local; // exclusive prefix for this chunk
    for (int i = 0; i < 32; ++i) {
        int c = g_cursor[base + i];
        g_rowptr[base + i] = run;
        g_cursor[base + i] = run; // reuse as fill cursor
        run += c;
    }
    if (tid == 511) g_rowptr[Vn] = run; // == Ee
}

__global__ void k_fill(const int* __restrict__ dst) {
    int e = blockIdx.x * blockDim.x + threadIdx.x;
    if (e < Ee) {
        int p = atomicAdd(&g_cursor[dst[e]], 1);
        g_eid[p] = e;
    }
}

// make accumulation order deterministic: sort each row's edge-id list ascending
__global__ void k_sortrows() {
    int v = blockIdx.x * blockDim.x + threadIdx.x;
    if (v >= Vn) return;
    int b = g_rowptr[v], en = g_rowptr[v + 1];
    for (int i = b + 1; i < en; ++i) {
        int key = g_eid[i];
        int j = i - 1;
        while (j >= b && g_eid[j] > key) { g_eid[j + 1] = g_eid[j]; --j; }
        g_eid[j + 1] = key;
    }
}

// ---------------- SpMM: X_nei[n, v, :] = sum_{e: dst=v} A[e] * X[n, src[e], :] ----------------
// one block per v, 128 threads = feature dim, 16 accumulators per thread (batch dim)
__global__ void k_spmm(const float* __restrict__ Xext, int use_ext,
                       const float* __restrict__ Avals, const int* __restrict__ esrc) {
    const float* __restrict__ X = use_ext ? Xext : g_x1;
    int v = blockIdx.x;
    int d = threadIdx.x;
    int beg = g_rowptr[v], end = g_rowptr[v + 1];

    float acc[Nb];
#pragma unroll
    for (int n = 0; n < Nb; ++n) acc[n] = 0.0f;

    __shared__ int   s_src[128];
    __shared__ float s_a[128];

    for (int cb = beg; cb < end; cb += 128) {
        int cnt = min(128, end - cb);
        __syncthreads();
        if (d < cnt) {
            int e = g_eid[cb + d];
            s_src[d] = esrc[e];
            s_a[d] = Avals[e];
        }
        __syncthreads();
        for (int t = 0; t < cnt; ++t) {
            float a = s_a[t];
            int base = s_src[t] * Dd + d;
#pragma unroll
            for (int n = 0; n < Nb; ++n)
                acc[n] += a * X[base + n * VD];
        }
    }
    int ob = v * Dd + d;
#pragma unroll
    for (int n = 0; n < Nb; ++n) g_nei[ob + n * VD] = acc[n];
}

// ---------------- GEMM: Y = X @ Ws^T + X_nei @ Wn^T  (+ fused BN stat partials) ----------------
// 128x128 output tile / block, BK=8, 256 threads, 8x8 micro-tile per thread.
__global__ void __launch_bounds__(256, 2)
k_gemm(const float* __restrict__ Xext, int x_ext,
       const float* __restrict__ W0, const float* __restrict__ W1,
       float* __restrict__ Yext, int y_ext) {
    const float* __restrict__ X0 = x_ext ? Xext : g_x1;
    float* __restrict__ Y = y_ext ? Yext : g_x1;

    __shared__ float As[8][128];
    __shared__ float Bs[8][128];
    __shared__ float s_sum[16][128];
    __shared__ float s_sq[16][128];

    int tid = threadIdx.x;
    int bx = blockIdx.x;
    int row0 = bx * 128;
    int tx = tid & 15;        // 0..15 -> cols tx*8..tx*8+7
    int ty = tid >> 4;        // 0..15 -> rows ty*8..ty*8+7
    int lr = tid >> 1;        // 0..127 loader row
    int lc = (tid & 1) * 4;   // 0 or 4 loader col

    float acc[8][8];
#pragma unroll
    for (int i = 0; i < 8; ++i)
#pragma unroll
        for (int j = 0; j < 8; ++j) acc[i][j] = 0.0f;

    const float* Xi[2] = {X0, g_nei};
    const float* Wi[2] = {W0, W1};

    for (int s = 0; s < 2; ++s) {
        const float* __restrict__ Xp = Xi[s];
        const float* __restrict__ Wp = Wi[s];
        for (int k0 = 0; k0 < 128; k0 += 8) {
            float4 av = *(const float4*)(Xp + (row0 + lr) * Dd + k0 + lc);
            float4 bv = *(const float4*)(Wp + lr * Dd + k0 + lc);
            __syncthreads();
            As[lc + 0][lr] = av.x; As[lc + 1][lr] = av.y;
            As[lc + 2][lr] = av.z; As[lc + 3][lr] = av.w;
            Bs[lc + 0][lr] = bv.x; Bs[lc + 1][lr] = bv.y;
            Bs[lc + 2][lr] = bv.z; Bs[lc + 3][lr] = bv.w;
            __syncthreads();
#pragma unroll
            for (int kk = 0; kk < 8; ++kk) {
                float a[8], b[8];
                *(float4*)(a)     = *(const float4*)&As[kk][ty * 8];
                *(float4*)(a + 4) = *(const float4*)&As[kk][ty * 8 + 4];
                *(float4*)(b)     = *(const float4*)&Bs[kk][tx * 8];
                *(float4*)(b + 4) = *(const float4*)&Bs[kk][tx * 8 + 4];
#pragma unroll
                for (int i = 0; i < 8; ++i)
#pragma unroll
                    for (int j = 0; j < 8; ++j)
                        acc[i][j] += a[i] * b[j];
            }
        }
    }

    // write Y
#pragma unroll
    for (int i = 0; i < 8; ++i) {
        int row = row0 + ty * 8 + i;
        float4 v0 = make_float4(acc[i][0], acc[i][1], acc[i][2], acc[i][3]);
        float4 v1 = make_float4(acc[i][4], acc[i][5], acc[i][6], acc[i][7]);
        *(float4*)(Y + row * Dd + tx * 8)     = v0;
        *(float4*)(Y + row * Dd + tx * 8 + 4) = v1;
    }

    // deterministic per-block BN stats: per-thread column sums -> smem -> fixed-order reduce
#pragma unroll
    for (int j = 0; j < 8; ++j) {
        float sv = 0.0f, qv = 0.0f;
#pragma unroll
        for (int i = 0; i < 8; ++i) { sv += acc[i][j]; qv += acc[i][j] * acc[i][j]; }
        s_sum[ty][tx * 8 + j] = sv;
        s_sq[ty][tx * 8 + j] = qv;
    }
    __syncthreads();
    if (tid < 128) {
        float sv = 0.0f, qv = 0.0f;
#pragma unroll
        for (int r = 0; r < 16; ++r) { sv += s_sum[r][tid]; qv += s_sq[r][tid]; }
        g_partial[bx * 256 + tid] = sv;
        g_partial[bx * 256 + 128 + tid] = qv;
    }
}

// ---------------- BN finalize: reduce partials (double), compute scale/shift ----------------
__global__ void k_bn_finalize(const float* __restrict__ gamma, const float* __restrict__ beta) {
    int d = threadIdx.x; // 128
    double s = 0.0, q = 0.0;
    for (int b = 0; b < GEMM_BLOCKS; ++b) {
        s += (double)g_partial[b * 256 + d];
        q += (double)g_partial[b * 256 + 128 + d];
    }
    const double M = (double)Mrows;
    double mean = s / M;
    double var = q / M - mean * mean;
    float sc = gamma[d] * (float)(1.0 / sqrt(var + EPSBN));
    g_scale[d] = sc;
    g_shift[d] = beta[d] - (float)mean * sc;
}

// ---------------- BN apply + ReLU (in place) ----------------
__global__ void k_bn_relu(float* __restrict__ Yext, int y_ext) {
    float* __restrict__ Y = y_ext ? Yext : g_x1;
    int i = blockIdx.x * blockDim.x + threadIdx.x; // over Mrows*Dd/4 float4s
    float4 y = ((const float4*)Y)[i];
    int d = (i & 31) * 4;
    y.x = fmaxf(0.0f, y.x * g_scale[d + 0] + g_shift[d + 0]);
    y.y = fmaxf(0.0f, y.y * g_scale[d + 1] + g_shift[d + 1]);
    y.z = fmaxf(0.0f, y.z * g_scale[d + 2] + g_shift[d + 2]);
    y.w = fmaxf(0.0f, y.w * g_scale[d + 3] + g_shift[d + 3]);
    ((float4*)Y)[i] = y;
}

// ---------------- launch ----------------
extern "C" void kernel_launch(void* const* d_in, const int* in_sizes, int n_in,
                              void* d_out, int out_size) {
    const float* H     = (const float*)d_in[0];
    const int*   esrc  = (const int*)d_in[1];
    const int*   edst  = (const int*)d_in[2];
    const float* Av    = (const float*)d_in[3];
    const float* Wself = (const float*)d_in[4];
    const float* Wnei  = (const float*)d_in[5];
    const float* gamma = (const float*)d_in[6];
    const float* beta  = (const float*)d_in[7];
    float* out = (float*)d_out;

    // CSR build (graph is an input; rebuild every launch, deterministic via row sort)
    k_zero_counts<<<Vn / 256, 256>>>();
    k_hist<<<Ee / 256, 256>>>(edst);
    k_scan<<<1, 512>>>();
    k_fill<<<Ee / 256, 256>>>(edst);
    k_sortrows<<<Vn / 128, 128>>>();

    for (int l = 0; l < Ll; ++l) {
        int x_ext = (l == 0) ? 1 : 0;      // layer 0 reads H, layer 1 reads g_x1
        int y_ext = (l == Ll - 1) ? 1 : 0; // last layer writes d_out, else g_x1
        k_spmm<<<Vn, 128>>>(H, x_ext, Av, esrc);
        k_gemm<<<GEMM_BLOCKS, 256>>>(H, x_ext,
                                     Wself + (size_t)l * Dd * Dd,
                                     Wnei  + (size_t)l * Dd * Dd,
                                     out, y_ext);
        k_bn_finalize<<<1, 128>>>(gamma + l * Dd, beta + l * Dd);
        k_bn_relu<<<(Mrows * Dd / 4) / 256, 256>>>(out, y_ext);
    }
}